// round 4
// baseline (speedup 1.0000x reference)
#include <cuda_runtime.h>
#include <mma.h>
#include <cstdint>

using namespace nvcuda;

// ---------------- problem constants ----------------
#define DIM      4096
#define EXPERTS  64
#define T_TOK    8192
#define BTOK     64                  // tokens per GEMM block
#define BK       32                  // fp32 k per stage
#define NSTAGE   (DIM / BK)          // 128
#define GTH      256                 // 8 warps
#define BT       64                  // post/loc tile
#define NB       (T_TOK / BT)        // 128
#define SUSCAP   4096
#define EPS_GAP  5e-4f

// smem: per buffer {A_hi, A_lo, W_hi, W_lo} each 64 x 36 floats
#define SSTR     36
#define ARR      (64 * SSTR)         // 2304 floats
#define BUFF     (4 * ARR)           // 9216 floats
#define SMEM_BYTES (2 * BUFF * 4)    // 73728 B

// ---------------- device scratch ----------------
__device__ float g_logits[T_TOK * EXPERTS];
__device__ float g_me[EXPERTS];
__device__ int   g_indices[T_TOK];
__device__ int   g_blockCounts[NB * EXPERTS];
__device__ int   g_blockOffsets[NB * EXPERTS];
__device__ int   g_nsus;
__device__ int   g_suspects[SUSCAP];

__device__ __forceinline__ float to_tf32(float x) {
    float r;
    asm("cvt.rna.tf32.f32 %0, %1;" : "=f"(r) : "f"(x));
    return r;
}

// ---------------- pass 0: zero me + suspect counter ----------------
__global__ void init_kernel() {
    if (threadIdx.x < EXPERTS) g_me[threadIdx.x] = 0.0f;
    if (threadIdx.x == 0) g_nsus = 0;
}

// ---------------- pass 1: 3xTF32 WMMA GEMM -> logits ----------------
__global__ __launch_bounds__(GTH, 1) void gemm_kernel(
    const float* __restrict__ A,     // [T][DIM]
    const float* __restrict__ W)     // [EXPERTS][DIM]
{
    extern __shared__ __align__(16) float sm[];
    const int tid = threadIdx.x;
    const int wid = tid >> 5;
    const int wr  = wid >> 1;        // warp row (0..3): 16-token group
    const int wc  = wid & 1;         // warp col (0..1): 32-expert group
    const int t0  = blockIdx.x * BTOK;

    float4 rA[2], rW[2];
    {
#pragma unroll
        for (int q = 0; q < 2; q++) {
            int f4 = q * GTH + tid;
            int row = f4 >> 3;
            int c = (f4 & 7) * 4;
            rA[q] = *reinterpret_cast<const float4*>(&A[(size_t)(t0 + row) * DIM + c]);
            rW[q] = *reinterpret_cast<const float4*>(&W[(size_t)row * DIM + c]);
        }
    }

    wmma::fragment<wmma::accumulator, 16, 16, 8, float> cf[2];
#pragma unroll
    for (int j = 0; j < 2; j++) wmma::fill_fragment(cf[j], 0.0f);

    for (int s = 0; s < NSTAGE; s++) {
        const int buf = s & 1;
        float* A_hi = sm + buf * BUFF;
        float* A_lo = A_hi + ARR;
        float* W_hi = A_hi + 2 * ARR;
        float* W_lo = A_hi + 3 * ARR;

        // split-store prefetched regs into smem
#pragma unroll
        for (int q = 0; q < 2; q++) {
            int f4 = q * GTH + tid;
            int row = f4 >> 3;
            int c = (f4 & 7) * 4;
            int base = row * SSTR + c;
            float4 h, l;
            h.x = to_tf32(rA[q].x); l.x = to_tf32(rA[q].x - h.x);
            h.y = to_tf32(rA[q].y); l.y = to_tf32(rA[q].y - h.y);
            h.z = to_tf32(rA[q].z); l.z = to_tf32(rA[q].z - h.z);
            h.w = to_tf32(rA[q].w); l.w = to_tf32(rA[q].w - h.w);
            *reinterpret_cast<float4*>(&A_hi[base]) = h;
            *reinterpret_cast<float4*>(&A_lo[base]) = l;
            h.x = to_tf32(rW[q].x); l.x = to_tf32(rW[q].x - h.x);
            h.y = to_tf32(rW[q].y); l.y = to_tf32(rW[q].y - h.y);
            h.z = to_tf32(rW[q].z); l.z = to_tf32(rW[q].z - h.z);
            h.w = to_tf32(rW[q].w); l.w = to_tf32(rW[q].w - h.w);
            *reinterpret_cast<float4*>(&W_hi[base]) = h;
            *reinterpret_cast<float4*>(&W_lo[base]) = l;
        }
        __syncthreads();

        if (s + 1 < NSTAGE) {
            const int k0 = (s + 1) * BK;
#pragma unroll
            for (int q = 0; q < 2; q++) {
                int f4 = q * GTH + tid;
                int row = f4 >> 3;
                int c = (f4 & 7) * 4;
                rA[q] = *reinterpret_cast<const float4*>(&A[(size_t)(t0 + row) * DIM + k0 + c]);
                rW[q] = *reinterpret_cast<const float4*>(&W[(size_t)row * DIM + k0 + c]);
            }
        }

#pragma unroll
        for (int k8 = 0; k8 < BK / 8; k8++) {
            wmma::fragment<wmma::matrix_a, 16, 16, 8, wmma::precision::tf32, wmma::row_major> aH, aL;
            const int r0 = wr * 16;
            wmma::load_matrix_sync(aH, &A_hi[r0 * SSTR + k8 * 8], SSTR);
            wmma::load_matrix_sync(aL, &A_lo[r0 * SSTR + k8 * 8], SSTR);
#pragma unroll
            for (int j = 0; j < 2; j++) {
                wmma::fragment<wmma::matrix_b, 16, 16, 8, wmma::precision::tf32, wmma::col_major> bH, bL;
                const int e0 = wc * 32 + j * 16;
                wmma::load_matrix_sync(bH, &W_hi[e0 * SSTR + k8 * 8], SSTR);
                wmma::load_matrix_sync(bL, &W_lo[e0 * SSTR + k8 * 8], SSTR);
                wmma::mma_sync(cf[j], aH, bH, cf[j]);
                wmma::mma_sync(cf[j], aH, bL, cf[j]);
                wmma::mma_sync(cf[j], aL, bH, cf[j]);
            }
        }
    }

#pragma unroll
    for (int j = 0; j < 2; j++)
        wmma::store_matrix_sync(
            &g_logits[(size_t)(t0 + wr * 16) * EXPERTS + wc * 32 + j * 16],
            cf[j], EXPERTS, wmma::mem_row_major);
}

// ---------------- pass 2: argmax/softmax/me + suspect detection ----------------
#define LS_STRIDE 68
__global__ void post_kernel(float* __restrict__ out, int T) {
    __shared__ float Ls[BT * LS_STRIDE];
    __shared__ float ms[BT];
    __shared__ float sums[BT];
    const int tid = threadIdx.x;        // 128 threads
    const int tok0 = blockIdx.x * BT;

#pragma unroll
    for (int q = 0; q < 8; q++) {
        int f4 = q * 128 + tid;
        int row = f4 >> 4, c4 = f4 & 15;
        float4 v = *reinterpret_cast<const float4*>(
            &g_logits[(size_t)(tok0 + row) * EXPERTS + c4 * 4]);
        *reinterpret_cast<float4*>(&Ls[row * LS_STRIDE + c4 * 4]) = v;
    }
    __syncthreads();

    if (tid < BT) {
        const int t = tid;
        float m = Ls[t * LS_STRIDE + 0];
        float m2 = -3.4e38f;
        int am = 0;
#pragma unroll 4
        for (int e = 1; e < EXPERTS; e++) {
            float v = Ls[t * LS_STRIDE + e];
            if (v > m) { m2 = m; m = v; am = e; }
            else if (v > m2) { m2 = v; }
        }
        float s = 0.0f;
#pragma unroll 4
        for (int e = 0; e < EXPERTS; e++)
            s += __expf(Ls[t * LS_STRIDE + e] - m);
        ms[t] = m;
        sums[t] = s;
        int gt = tok0 + t;
        g_indices[gt]       = am;
        out[1 + gt]         = (float)am;
        out[1 + 2 * T + gt] = 1.0f / s;
        if (m - m2 < EPS_GAP) {
            int i = atomicAdd(&g_nsus, 1);
            if (i < SUSCAP) g_suspects[i] = gt;
        }
    }
    __syncthreads();

    if (tid < EXPERTS) {
        const int e = tid;
        float acc = 0.0f;
#pragma unroll 4
        for (int t = 0; t < BT; t++)
            acc += __expf(Ls[t * LS_STRIDE + e] - ms[t]) / sums[t];
        atomicAdd(&g_me[e], acc);
    }
}

// ---------------- pass 3: exact fp64 rescue for near-tie tokens ----------------
__global__ void rescue_kernel(const float* __restrict__ A,
                              const float* __restrict__ W,
                              float* __restrict__ out, int T) {
    __shared__ double bv[8];
    __shared__ int    bi[8];
    const int wid = threadIdx.x >> 5;
    const int lane = threadIdx.x & 31;
    int n = g_nsus;
    if (n > SUSCAP) n = SUSCAP;

    for (int s = 0; s < n; s++) {
        const int t = g_suspects[s];
        double best = -1e300;
        int besti = 0;
        const float* ap = A + (size_t)t * DIM;
#pragma unroll 1
        for (int sub = 0; sub < 8; sub++) {
            const int e = wid * 8 + sub;
            const float* wp = W + (size_t)e * DIM;
            double acc = 0.0;
            for (int k = lane; k < DIM; k += 32)
                acc += (double)ap[k] * (double)wp[k];
#pragma unroll
            for (int o = 16; o; o >>= 1)
                acc += __shfl_down_sync(0xffffffffu, acc, o);
            acc = __shfl_sync(0xffffffffu, acc, 0);
            if (acc > best) { best = acc; besti = e; }   // ascending e: first-max
        }
        if (lane == 0) { bv[wid] = best; bi[wid] = besti; }
        __syncthreads();
        if (threadIdx.x == 0) {
            double m = bv[0]; int am = bi[0];
            for (int w = 1; w < 8; w++)
                if (bv[w] > m) { m = bv[w]; am = bi[w]; }
            g_indices[t] = am;
            out[1 + t] = (float)am;
            const float* L = &g_logits[(size_t)t * EXPERTS];
            float mx = L[0];
            for (int e = 1; e < EXPERTS; e++) mx = fmaxf(mx, L[e]);
            float den = 0.0f;
            for (int e = 0; e < EXPERTS; e++) den += __expf(L[e] - mx);
            out[1 + 2 * T + t] = __expf(L[am] - mx) / den;
        }
        __syncthreads();
    }
}

// ---------------- pass 4: per-block expert histogram ----------------
__global__ void count_kernel() {
    __shared__ int h[EXPERTS];
    const int t = threadIdx.x;          // 64 threads
    h[t] = 0;
    __syncthreads();
    atomicAdd(&h[g_indices[blockIdx.x * BT + t]], 1);
    __syncthreads();
    g_blockCounts[blockIdx.x * EXPERTS + t] = h[t];
}

// ---------------- pass 5: scan + l_aux ----------------
__global__ void gate_scan(float* __restrict__ out, int T, int nB) {
    __shared__ float red[EXPERTS];
    const int e = threadIdx.x;
    int run = 0;
    for (int b = 0; b < nB; b++) {
        g_blockOffsets[b * EXPERTS + e] = run;
        run += g_blockCounts[b * EXPERTS + e];
    }
    red[e] = g_me[e] * (float)run;
    __syncthreads();
    for (int s = EXPERTS / 2; s > 0; s >>= 1) {
        if (e < s) red[e] += red[e + s];
        __syncthreads();
    }
    if (e == 0)
        out[0] = red[0] * ((float)EXPERTS / ((float)T * (float)T));
}

// ---------------- pass 6: per-token location ----------------
__global__ void gate_loc(float* __restrict__ out, int T) {
    __shared__ int w0cnt[EXPERTS];
    const int b = blockIdx.x;
    const int t = threadIdx.x;
    const int gt = b * BT + t;
    const int e = g_indices[gt];
    const int lane = t & 31;
    const int warp = t >> 5;

    w0cnt[t] = 0;
    __syncthreads();

    unsigned peers = __match_any_sync(0xffffffffu, e);
    int rank = __popc(peers & ((1u << lane) - 1u));
    if (warp == 0 && lane == (__ffs(peers) - 1))
        w0cnt[e] = __popc(peers);
    __syncthreads();

    int loc = g_blockOffsets[b * EXPERTS + e] + rank + (warp ? w0cnt[e] : 0);
    out[1 + T + gt] = (float)loc;
}

// ---------------- launch ----------------
extern "C" void kernel_launch(void* const* d_in, const int* in_sizes, int n_in,
                              void* d_out, int out_size) {
    const float* A = (const float*)d_in[0];
    const float* W = (const float*)d_in[1];
    float* out = (float*)d_out;
    const int T = in_sizes[0] / DIM;        // 8192

    cudaFuncSetAttribute(gemm_kernel, cudaFuncAttributeMaxDynamicSharedMemorySize,
                         SMEM_BYTES);

    init_kernel<<<1, 64>>>();
    gemm_kernel<<<T / BTOK, GTH, SMEM_BYTES>>>(A, W);
    post_kernel<<<T / BT, 128>>>(out, T);
    rescue_kernel<<<1, 256>>>(A, W, out, T);
    count_kernel<<<T / BT, BT>>>();
    gate_scan<<<1, EXPERTS>>>(out, T, T / BT);
    gate_loc<<<T / BT, BT>>>(out, T);
}

// round 5
// speedup vs baseline: 3.7942x; 3.7942x over previous
#include <cuda_runtime.h>
#include <cstdint>

// ---------------- problem constants ----------------
#define DIM      4096
#define EXPERTS  64
#define T_TOK    8192
#define MB       128                 // tokens per GEMM block
#define KSPL     2
#define KHALF    (DIM / KSPL)        // 2048
#define BK       16                  // k per stage
#define NSTAGE   (KHALF / BK)        // 128
#define GTH      256                 // 8 warps
#define BT       64
#define NB       (T_TOK / BT)        // 128
#define SUSCAP   2048
#define EPS_GAP  2e-4f

// smem layout (float offsets), KSTR=20 padded rows -> conflict-free frag loads
#define KSTR     20
#define OFF_AH   0
#define OFF_AL   2560                // 128*20
#define OFF_WH   5120
#define OFF_WL   6400                // +64*20
#define BUFSZ    7680
#define SMEM_BYTES (2 * BUFSZ * 4)   // 61440

// ---------------- device scratch ----------------
__device__ float g_logits[T_TOK * EXPERTS];
__device__ float g_me[EXPERTS];
__device__ int   g_indices[T_TOK];
__device__ int   g_blockCounts[NB * EXPERTS];
__device__ int   g_blockOffsets[NB * EXPERTS];
__device__ int   g_nsus;
__device__ int   g_suspects[SUSCAP];

__device__ __forceinline__ float to_tf32(float x) {
    float r;
    asm("cvt.rna.tf32.f32 %0, %1;" : "=f"(r) : "f"(x));
    return r;
}

#define MMA_TF32(d, a, b0, b1)                                               \
    asm volatile(                                                            \
        "mma.sync.aligned.m16n8k8.row.col.f32.tf32.tf32.f32 "                \
        "{%0,%1,%2,%3}, {%4,%5,%6,%7}, {%8,%9}, {%0,%1,%2,%3};"              \
        : "+f"((d)[0]), "+f"((d)[1]), "+f"((d)[2]), "+f"((d)[3])             \
        : "r"(__float_as_uint((a)[0])), "r"(__float_as_uint((a)[1])),        \
          "r"(__float_as_uint((a)[2])), "r"(__float_as_uint((a)[3])),        \
          "r"(__float_as_uint(b0)), "r"(__float_as_uint(b1)))

// ---------------- pass 0: zero logits + me + suspect counter ----------------
__global__ void init_kernel() {
    int i = blockIdx.x * blockDim.x + threadIdx.x;
    int stride = gridDim.x * blockDim.x;
    for (int j = i; j < T_TOK * EXPERTS; j += stride) g_logits[j] = 0.0f;
    if (i < EXPERTS) g_me[i] = 0.0f;
    if (i == 0) g_nsus = 0;
}

// ---------------- pass 1: 3xTF32 mma.sync GEMM -> logits (atomic combine) ----
__global__ __launch_bounds__(GTH, 1) void gemm_kernel(
    const float* __restrict__ A,     // [T][DIM]
    const float* __restrict__ W)     // [EXPERTS][DIM]
{
    extern __shared__ __align__(16) float sm[];
    const int tid  = threadIdx.x;
    const int lane = tid & 31;
    const int wid  = tid >> 5;
    const int wm   = wid >> 1;       // 0..3 : token group (32 tokens)
    const int wn   = wid & 1;        // 0..1 : expert group (32 experts)
    const int t0   = blockIdx.x * MB;
    const int kb   = blockIdx.y * KHALF;

    float acc[2][4][4];
#pragma unroll
    for (int mi = 0; mi < 2; mi++)
#pragma unroll
        for (int ni = 0; ni < 4; ni++)
#pragma unroll
            for (int r = 0; r < 4; r++) acc[mi][ni][r] = 0.0f;

    // prefetch registers
    float4 pA[2], pW;
    {
#pragma unroll
        for (int q = 0; q < 2; q++) {
            int f4 = q * GTH + tid;
            int row = f4 >> 2, c = (f4 & 3) * 4;
            pA[q] = *reinterpret_cast<const float4*>(&A[(size_t)(t0 + row) * DIM + kb + c]);
        }
        int row = tid >> 2, c = (tid & 3) * 4;
        pW = *reinterpret_cast<const float4*>(&W[(size_t)row * DIM + kb + c]);
    }

    for (int s = 0; s < NSTAGE; s++) {
        float* buf = sm + (s & 1) * BUFSZ;

        // ---- split-store prefetched tiles ----
#pragma unroll
        for (int q = 0; q < 2; q++) {
            int f4 = q * GTH + tid;
            int row = f4 >> 2, c = (f4 & 3) * 4;
            int base = row * KSTR + c;
            float4 h, l;
            h.x = to_tf32(pA[q].x); l.x = to_tf32(pA[q].x - h.x);
            h.y = to_tf32(pA[q].y); l.y = to_tf32(pA[q].y - h.y);
            h.z = to_tf32(pA[q].z); l.z = to_tf32(pA[q].z - h.z);
            h.w = to_tf32(pA[q].w); l.w = to_tf32(pA[q].w - h.w);
            *reinterpret_cast<float4*>(&buf[OFF_AH + base]) = h;
            *reinterpret_cast<float4*>(&buf[OFF_AL + base]) = l;
        }
        {
            int row = tid >> 2, c = (tid & 3) * 4;
            int base = row * KSTR + c;
            float4 h, l;
            h.x = to_tf32(pW.x); l.x = to_tf32(pW.x - h.x);
            h.y = to_tf32(pW.y); l.y = to_tf32(pW.y - h.y);
            h.z = to_tf32(pW.z); l.z = to_tf32(pW.z - h.z);
            h.w = to_tf32(pW.w); l.w = to_tf32(pW.w - h.w);
            *reinterpret_cast<float4*>(&buf[OFF_WH + base]) = h;
            *reinterpret_cast<float4*>(&buf[OFF_WL + base]) = l;
        }
        __syncthreads();

        // ---- prefetch next stage ----
        if (s + 1 < NSTAGE) {
            const int k0 = kb + (s + 1) * BK;
#pragma unroll
            for (int q = 0; q < 2; q++) {
                int f4 = q * GTH + tid;
                int row = f4 >> 2, c = (f4 & 3) * 4;
                pA[q] = *reinterpret_cast<const float4*>(&A[(size_t)(t0 + row) * DIM + k0 + c]);
            }
            int row = tid >> 2, c = (tid & 3) * 4;
            pW = *reinterpret_cast<const float4*>(&W[(size_t)row * DIM + k0 + c]);
        }

        // ---- compute 2 k8 steps ----
#pragma unroll
        for (int k8 = 0; k8 < BK; k8 += 8) {
            float aH[2][4], aL[2][4];
#pragma unroll
            for (int mi = 0; mi < 2; mi++) {
                int r = wm * 32 + mi * 16 + (lane >> 2);
                int c = k8 + (lane & 3);
                int b0 = r * KSTR + c;
                aH[mi][0] = buf[OFF_AH + b0];
                aH[mi][1] = buf[OFF_AH + b0 + 8 * KSTR];
                aH[mi][2] = buf[OFF_AH + b0 + 4];
                aH[mi][3] = buf[OFF_AH + b0 + 8 * KSTR + 4];
                aL[mi][0] = buf[OFF_AL + b0];
                aL[mi][1] = buf[OFF_AL + b0 + 8 * KSTR];
                aL[mi][2] = buf[OFF_AL + b0 + 4];
                aL[mi][3] = buf[OFF_AL + b0 + 8 * KSTR + 4];
            }
#pragma unroll
            for (int ni = 0; ni < 4; ni++) {
                int n = wn * 32 + ni * 8 + (lane >> 2);
                int kk = k8 + (lane & 3);
                int bb = n * KSTR + kk;
                float bH0 = buf[OFF_WH + bb], bH1 = buf[OFF_WH + bb + 4];
                float bL0 = buf[OFF_WL + bb], bL1 = buf[OFF_WL + bb + 4];
#pragma unroll
                for (int mi = 0; mi < 2; mi++) {
                    MMA_TF32(acc[mi][ni], aH[mi], bH0, bH1);
                    MMA_TF32(acc[mi][ni], aH[mi], bL0, bL1);
                    MMA_TF32(acc[mi][ni], aL[mi], bH0, bH1);
                }
            }
        }
    }

    // ---- epilogue: atomic combine of the two K halves ----
#pragma unroll
    for (int mi = 0; mi < 2; mi++) {
        int rbase = t0 + wm * 32 + mi * 16 + (lane >> 2);
#pragma unroll
        for (int ni = 0; ni < 4; ni++) {
            int cbase = wn * 32 + ni * 8 + (lane & 3) * 2;
            atomicAdd(&g_logits[(size_t)rbase * EXPERTS + cbase],           acc[mi][ni][0]);
            atomicAdd(&g_logits[(size_t)rbase * EXPERTS + cbase + 1],       acc[mi][ni][1]);
            atomicAdd(&g_logits[(size_t)(rbase + 8) * EXPERTS + cbase],     acc[mi][ni][2]);
            atomicAdd(&g_logits[(size_t)(rbase + 8) * EXPERTS + cbase + 1], acc[mi][ni][3]);
        }
    }
}

// ---------------- pass 2: argmax/softmax/me + suspect detection ----------------
#define LS_STRIDE 68
__global__ void post_kernel(float* __restrict__ out, int T) {
    __shared__ float Ls[BT * LS_STRIDE];
    __shared__ float ms[BT];
    __shared__ float sums[BT];
    const int tid = threadIdx.x;        // 128 threads
    const int tok0 = blockIdx.x * BT;

#pragma unroll
    for (int q = 0; q < 8; q++) {
        int f4 = q * 128 + tid;
        int row = f4 >> 4, c4 = f4 & 15;
        float4 v = *reinterpret_cast<const float4*>(
            &g_logits[(size_t)(tok0 + row) * EXPERTS + c4 * 4]);
        *reinterpret_cast<float4*>(&Ls[row * LS_STRIDE + c4 * 4]) = v;
    }
    __syncthreads();

    if (tid < BT) {
        const int t = tid;
        float m = Ls[t * LS_STRIDE + 0];
        float m2 = -3.4e38f;
        int am = 0;
#pragma unroll 4
        for (int e = 1; e < EXPERTS; e++) {
            float v = Ls[t * LS_STRIDE + e];
            if (v > m) { m2 = m; m = v; am = e; }
            else if (v > m2) { m2 = v; }
        }
        float s = 0.0f;
#pragma unroll 4
        for (int e = 0; e < EXPERTS; e++)
            s += __expf(Ls[t * LS_STRIDE + e] - m);
        ms[t] = m;
        sums[t] = s;
        int gt = tok0 + t;
        g_indices[gt]       = am;
        out[1 + gt]         = (float)am;
        out[1 + 2 * T + gt] = 1.0f / s;
        if (m - m2 < EPS_GAP) {
            int i = atomicAdd(&g_nsus, 1);
            if (i < SUSCAP) g_suspects[i] = gt;
        }
    }
    __syncthreads();

    if (tid < EXPERTS) {
        const int e = tid;
        float acc = 0.0f;
#pragma unroll 4
        for (int t = 0; t < BT; t++)
            acc += __expf(Ls[t * LS_STRIDE + e] - ms[t]) / sums[t];
        atomicAdd(&g_me[e], acc);
    }
}

// ---------------- pass 3: exact fp64 rescue, parallel over suspects ----------
__global__ void rescue_kernel(const float* __restrict__ A,
                              const float* __restrict__ W,
                              float* __restrict__ out, int T) {
    __shared__ double bv[8];
    __shared__ int    bi[8];
    const int wid = threadIdx.x >> 5;   // 8 warps
    const int lane = threadIdx.x & 31;
    int n = g_nsus;
    if (n > SUSCAP) n = SUSCAP;

    for (int s = blockIdx.x; s < n; s += gridDim.x) {
        const int t = g_suspects[s];
        const float* ap = A + (size_t)t * DIM;
        double best = -1e300;
        int besti = 0;
#pragma unroll 1
        for (int sub = 0; sub < 8; sub++) {
            const int e = wid * 8 + sub;
            const float* wp = W + (size_t)e * DIM;
            double a0 = 0.0, a1 = 0.0, a2 = 0.0, a3 = 0.0;
#pragma unroll 4
            for (int i = 0; i < DIM / 128; i++) {
                int k = (i * 32 + lane) * 4;
                float4 av = *reinterpret_cast<const float4*>(ap + k);
                float4 wv = *reinterpret_cast<const float4*>(wp + k);
                a0 += (double)av.x * (double)wv.x;
                a1 += (double)av.y * (double)wv.y;
                a2 += (double)av.z * (double)wv.z;
                a3 += (double)av.w * (double)wv.w;
            }
            double acc = (a0 + a1) + (a2 + a3);
#pragma unroll
            for (int o = 16; o; o >>= 1)
                acc += __shfl_down_sync(0xffffffffu, acc, o);
            acc = __shfl_sync(0xffffffffu, acc, 0);
            if (acc > best) { best = acc; besti = e; }   // ascending e: first-max
        }
        if (lane == 0) { bv[wid] = best; bi[wid] = besti; }
        __syncthreads();
        if (threadIdx.x == 0) {
            double m = bv[0]; int am = bi[0];
            for (int w = 1; w < 8; w++)
                if (bv[w] > m) { m = bv[w]; am = bi[w]; }
            g_indices[t] = am;
            out[1 + t] = (float)am;
            const float* L = &g_logits[(size_t)t * EXPERTS];
            float mx = L[0];
            for (int e = 1; e < EXPERTS; e++) mx = fmaxf(mx, L[e]);
            float den = 0.0f;
            for (int e = 0; e < EXPERTS; e++) den += __expf(L[e] - mx);
            out[1 + 2 * T + t] = __expf(L[am] - mx) / den;
        }
        __syncthreads();
    }
}

// ---------------- pass 4: per-block expert histogram (post-rescue) ----------
__global__ void count_kernel() {
    __shared__ int h[EXPERTS];
    const int t = threadIdx.x;          // 64 threads
    h[t] = 0;
    __syncthreads();
    atomicAdd(&h[g_indices[blockIdx.x * BT + t]], 1);
    __syncthreads();
    g_blockCounts[blockIdx.x * EXPERTS + t] = h[t];
}

// ---------------- pass 5: scan + l_aux ----------------
__global__ void gate_scan(float* __restrict__ out, int T, int nB) {
    __shared__ float red[EXPERTS];
    const int e = threadIdx.x;
    int run = 0;
    for (int b = 0; b < nB; b++) {
        g_blockOffsets[b * EXPERTS + e] = run;
        run += g_blockCounts[b * EXPERTS + e];
    }
    red[e] = g_me[e] * (float)run;
    __syncthreads();
    for (int s = EXPERTS / 2; s > 0; s >>= 1) {
        if (e < s) red[e] += red[e + s];
        __syncthreads();
    }
    if (e == 0)
        out[0] = red[0] * ((float)EXPERTS / ((float)T * (float)T));
}

// ---------------- pass 6: per-token location ----------------
__global__ void gate_loc(float* __restrict__ out, int T) {
    __shared__ int w0cnt[EXPERTS];
    const int b = blockIdx.x;
    const int t = threadIdx.x;
    const int gt = b * BT + t;
    const int e = g_indices[gt];
    const int lane = t & 31;
    const int warp = t >> 5;

    w0cnt[t] = 0;
    __syncthreads();

    unsigned peers = __match_any_sync(0xffffffffu, e);
    int rank = __popc(peers & ((1u << lane) - 1u));
    if (warp == 0 && lane == (__ffs(peers) - 1))
        w0cnt[e] = __popc(peers);
    __syncthreads();

    int loc = g_blockOffsets[b * EXPERTS + e] + rank + (warp ? w0cnt[e] : 0);
    out[1 + T + gt] = (float)loc;
}

// ---------------- launch ----------------
extern "C" void kernel_launch(void* const* d_in, const int* in_sizes, int n_in,
                              void* d_out, int out_size) {
    const float* A = (const float*)d_in[0];
    const float* W = (const float*)d_in[1];
    float* out = (float*)d_out;
    const int T = in_sizes[0] / DIM;        // 8192

    cudaFuncSetAttribute(gemm_kernel, cudaFuncAttributeMaxDynamicSharedMemorySize,
                         SMEM_BYTES);

    init_kernel<<<256, 256>>>();
    dim3 grid(T / MB, KSPL);
    gemm_kernel<<<grid, GTH, SMEM_BYTES>>>(A, W);
    post_kernel<<<T / BT, 128>>>(out, T);
    rescue_kernel<<<128, 256>>>(A, W, out, T);
    count_kernel<<<T / BT, BT>>>();
    gate_scan<<<1, EXPERTS>>>(out, T, T / BT);
    gate_loc<<<T / BT, BT>>>(out, T);
}

// round 6
// speedup vs baseline: 11.4758x; 3.0246x over previous
#include <cuda_runtime.h>
#include <cstdint>

// ---------------- problem constants ----------------
#define DIM      4096
#define EXPERTS  64
#define T_TOK    8192
#define MB       64                  // tokens per GEMM block
#define BK       32                  // k per stage
#define NSTAGE   (DIM / BK)          // 128
#define GTH      128                 // 4 warps
#define BT       64
#define NB       (T_TOK / BT)        // 128
#define SUSCAP   2048
#define EPS_GAP  1e-4f

// smem layout (float offsets), KSTR=36 padded rows -> conflict-free frag loads
#define KSTR     36
#define OFF_AH   0
#define OFF_AL   2304                // 64*36
#define OFF_WH   4608
#define OFF_WL   6912
#define BUFSZ    9216
#define SMEM_BYTES (2 * BUFSZ * 4)   // 73728 B

// ---------------- device scratch ----------------
__device__ float g_logits[T_TOK * EXPERTS];
__device__ float g_me[EXPERTS];
__device__ int   g_indices[T_TOK];
__device__ int   g_blockCounts[NB * EXPERTS];
__device__ int   g_blockOffsets[NB * EXPERTS];
__device__ int   g_nsus;
__device__ int   g_suspects[SUSCAP];

__device__ __forceinline__ float to_tf32(float x) {
    float r;
    asm("cvt.rna.tf32.f32 %0, %1;" : "=f"(r) : "f"(x));
    return r;
}

#define MMA_TF32(d, a, b0, b1)                                               \
    asm volatile(                                                            \
        "mma.sync.aligned.m16n8k8.row.col.f32.tf32.tf32.f32 "                \
        "{%0,%1,%2,%3}, {%4,%5,%6,%7}, {%8,%9}, {%0,%1,%2,%3};"              \
        : "+f"((d)[0]), "+f"((d)[1]), "+f"((d)[2]), "+f"((d)[3])             \
        : "r"(__float_as_uint((a)[0])), "r"(__float_as_uint((a)[1])),        \
          "r"(__float_as_uint((a)[2])), "r"(__float_as_uint((a)[3])),        \
          "r"(__float_as_uint(b0)), "r"(__float_as_uint(b1)))

// ---------------- pass 0: zero me + suspect counter ----------------
__global__ void init_kernel() {
    int i = threadIdx.x;
    if (i < EXPERTS) g_me[i] = 0.0f;
    if (i == 0) g_nsus = 0;
}

// ---------------- pass 1: 3xTF32 mma.sync GEMM (full K, direct store) -------
__global__ __launch_bounds__(GTH, 1) void gemm_kernel(
    const float* __restrict__ A,     // [T][DIM]
    const float* __restrict__ W)     // [EXPERTS][DIM]
{
    extern __shared__ __align__(16) float sm[];
    const int tid  = threadIdx.x;
    const int lane = tid & 31;
    const int wid  = tid >> 5;       // 4 warps
    const int wm   = wid >> 1;       // 0..1 : 32-token group
    const int wn   = wid & 1;        // 0..1 : 32-expert group
    const int t0   = blockIdx.x * MB;

    float acc[2][4][4];
#pragma unroll
    for (int mi = 0; mi < 2; mi++)
#pragma unroll
        for (int ni = 0; ni < 4; ni++)
#pragma unroll
            for (int r = 0; r < 4; r++) acc[mi][ni][r] = 0.0f;

    // prefetch registers: 4 float4 A + 4 float4 W per thread per stage
    float4 pA[4], pW[4];
#pragma unroll
    for (int q = 0; q < 4; q++) {
        int f4 = q * GTH + tid;
        int row = f4 >> 3, c = (f4 & 7) * 4;
        pA[q] = *reinterpret_cast<const float4*>(&A[(size_t)(t0 + row) * DIM + c]);
        pW[q] = *reinterpret_cast<const float4*>(&W[(size_t)row * DIM + c]);
    }

    for (int s = 0; s < NSTAGE; s++) {
        float* buf = sm + (s & 1) * BUFSZ;

        // ---- split-store prefetched tiles ----
#pragma unroll
        for (int q = 0; q < 4; q++) {
            int f4 = q * GTH + tid;
            int row = f4 >> 3, c = (f4 & 7) * 4;
            int base = row * KSTR + c;
            float4 h, l;
            h.x = to_tf32(pA[q].x); l.x = to_tf32(pA[q].x - h.x);
            h.y = to_tf32(pA[q].y); l.y = to_tf32(pA[q].y - h.y);
            h.z = to_tf32(pA[q].z); l.z = to_tf32(pA[q].z - h.z);
            h.w = to_tf32(pA[q].w); l.w = to_tf32(pA[q].w - h.w);
            *reinterpret_cast<float4*>(&buf[OFF_AH + base]) = h;
            *reinterpret_cast<float4*>(&buf[OFF_AL + base]) = l;
            h.x = to_tf32(pW[q].x); l.x = to_tf32(pW[q].x - h.x);
            h.y = to_tf32(pW[q].y); l.y = to_tf32(pW[q].y - h.y);
            h.z = to_tf32(pW[q].z); l.z = to_tf32(pW[q].z - h.z);
            h.w = to_tf32(pW[q].w); l.w = to_tf32(pW[q].w - h.w);
            *reinterpret_cast<float4*>(&buf[OFF_WH + base]) = h;
            *reinterpret_cast<float4*>(&buf[OFF_WL + base]) = l;
        }
        __syncthreads();

        // ---- prefetch next stage ----
        if (s + 1 < NSTAGE) {
            const int k0 = (s + 1) * BK;
#pragma unroll
            for (int q = 0; q < 4; q++) {
                int f4 = q * GTH + tid;
                int row = f4 >> 3, c = (f4 & 7) * 4;
                pA[q] = *reinterpret_cast<const float4*>(&A[(size_t)(t0 + row) * DIM + k0 + c]);
                pW[q] = *reinterpret_cast<const float4*>(&W[(size_t)row * DIM + k0 + c]);
            }
        }

        // ---- compute 4 k8 steps ----
#pragma unroll
        for (int k8 = 0; k8 < BK; k8 += 8) {
            float aH[2][4], aL[2][4];
#pragma unroll
            for (int mi = 0; mi < 2; mi++) {
                int r = wm * 32 + mi * 16 + (lane >> 2);
                int c = k8 + (lane & 3);
                int b0 = r * KSTR + c;
                aH[mi][0] = buf[OFF_AH + b0];
                aH[mi][1] = buf[OFF_AH + b0 + 8 * KSTR];
                aH[mi][2] = buf[OFF_AH + b0 + 4];
                aH[mi][3] = buf[OFF_AH + b0 + 8 * KSTR + 4];
                aL[mi][0] = buf[OFF_AL + b0];
                aL[mi][1] = buf[OFF_AL + b0 + 8 * KSTR];
                aL[mi][2] = buf[OFF_AL + b0 + 4];
                aL[mi][3] = buf[OFF_AL + b0 + 8 * KSTR + 4];
            }
#pragma unroll
            for (int ni = 0; ni < 4; ni++) {
                int n = wn * 32 + ni * 8 + (lane >> 2);
                int kk = k8 + (lane & 3);
                int bb = n * KSTR + kk;
                float bH0 = buf[OFF_WH + bb], bH1 = buf[OFF_WH + bb + 4];
                float bL0 = buf[OFF_WL + bb], bL1 = buf[OFF_WL + bb + 4];
#pragma unroll
                for (int mi = 0; mi < 2; mi++) {
                    MMA_TF32(acc[mi][ni], aH[mi], bH0, bH1);
                    MMA_TF32(acc[mi][ni], aH[mi], bL0, bL1);
                    MMA_TF32(acc[mi][ni], aL[mi], bH0, bH1);
                }
            }
        }
        __syncthreads();
    }

    // ---- epilogue: direct store ----
#pragma unroll
    for (int mi = 0; mi < 2; mi++) {
        int rbase = t0 + wm * 32 + mi * 16 + (lane >> 2);
#pragma unroll
        for (int ni = 0; ni < 4; ni++) {
            int cbase = wn * 32 + ni * 8 + (lane & 3) * 2;
            *reinterpret_cast<float2*>(&g_logits[(size_t)rbase * EXPERTS + cbase]) =
                make_float2(acc[mi][ni][0], acc[mi][ni][1]);
            *reinterpret_cast<float2*>(&g_logits[(size_t)(rbase + 8) * EXPERTS + cbase]) =
                make_float2(acc[mi][ni][2], acc[mi][ni][3]);
        }
    }
}

// ---------------- pass 2: argmax/softmax/me + suspect detection --------------
#define LS_STRIDE 68
__global__ void post_kernel(float* __restrict__ out, int T) {
    __shared__ float Ls[BT * LS_STRIDE];
    __shared__ float ms[BT];
    __shared__ float sums[BT];
    const int tid = threadIdx.x;        // 128 threads
    const int tok0 = blockIdx.x * BT;

#pragma unroll
    for (int q = 0; q < 8; q++) {
        int f4 = q * 128 + tid;
        int row = f4 >> 4, c4 = f4 & 15;
        float4 v = *reinterpret_cast<const float4*>(
            &g_logits[(size_t)(tok0 + row) * EXPERTS + c4 * 4]);
        *reinterpret_cast<float4*>(&Ls[row * LS_STRIDE + c4 * 4]) = v;
    }
    __syncthreads();

    if (tid < BT) {
        const int t = tid;
        float m = Ls[t * LS_STRIDE + 0];
        float m2 = -3.4e38f;
        int am = 0;
#pragma unroll 4
        for (int e = 1; e < EXPERTS; e++) {
            float v = Ls[t * LS_STRIDE + e];
            if (v > m) { m2 = m; m = v; am = e; }
            else if (v > m2) { m2 = v; }
        }
        float s = 0.0f;
#pragma unroll 4
        for (int e = 0; e < EXPERTS; e++)
            s += __expf(Ls[t * LS_STRIDE + e] - m);
        ms[t] = m;
        sums[t] = s;
        int gt = tok0 + t;
        g_indices[gt]       = am;
        out[1 + gt]         = (float)am;
        out[1 + 2 * T + gt] = 1.0f / s;
        if (m - m2 < EPS_GAP) {
            int i = atomicAdd(&g_nsus, 1);
            if (i < SUSCAP) g_suspects[i] = gt;
        }
    }
    __syncthreads();

    if (tid < EXPERTS) {
        const int e = tid;
        float acc = 0.0f;
#pragma unroll 4
        for (int t = 0; t < BT; t++)
            acc += __expf(Ls[t * LS_STRIDE + e] - ms[t]) / sums[t];
        atomicAdd(&g_me[e], acc);
    }
}

// ---------------- pass 3: double-single fp32 rescue (candidates only) --------
__device__ __forceinline__ void two_sum(float a, float b, float& s, float& e) {
    s = a + b;
    float bb = s - a;
    e = (a - (s - bb)) + (b - bb);
}

__global__ void rescue_kernel(const float* __restrict__ A,
                              const float* __restrict__ W,
                              float* __restrict__ out, int T) {
    __shared__ float Lsm[EXPERTS];
    __shared__ double bv[8];
    __shared__ int    bi[8];
    const int wid = threadIdx.x >> 5;   // 8 warps
    const int lane = threadIdx.x & 31;
    int n = g_nsus;
    if (n > SUSCAP) n = SUSCAP;

    for (int s = blockIdx.x; s < n; s += gridDim.x) {
        const int t = g_suspects[s];
        const float* ap = A + (size_t)t * DIM;

        if (threadIdx.x < EXPERTS) Lsm[threadIdx.x] = g_logits[(size_t)t * EXPERTS + threadIdx.x];
        __syncthreads();
        float mx32 = Lsm[0];
        for (int e = 1; e < EXPERTS; e++) mx32 = fmaxf(mx32, Lsm[e]);
        const float win = mx32 - 2.0f * EPS_GAP;

        double best = -1e300;
        int besti = EXPERTS;
#pragma unroll 1
        for (int sub = 0; sub < 8; sub++) {
            const int e = wid * 8 + sub;
            if (Lsm[e] < win) continue;       // not a candidate
            const float* wp = W + (size_t)e * DIM;
            float sacc = 0.0f, cacc = 0.0f;
#pragma unroll 4
            for (int i = 0; i < DIM / 128; i++) {
                int k = (i * 32 + lane) * 4;
                float4 av = *reinterpret_cast<const float4*>(ap + k);
                float4 wv = *reinterpret_cast<const float4*>(wp + k);
#pragma unroll
                for (int j = 0; j < 4; j++) {
                    float a = (&av.x)[j], b = (&wv.x)[j];
                    float p = a * b;
                    float pe = fmaf(a, b, -p);
                    float tnew, err;
                    two_sum(sacc, p, tnew, err);
                    cacc += err + pe;
                    sacc = tnew;
                }
            }
            // warp reduce (s, c)
#pragma unroll
            for (int o = 16; o; o >>= 1) {
                float sh = __shfl_down_sync(0xffffffffu, sacc, o);
                float ch = __shfl_down_sync(0xffffffffu, cacc, o);
                float tnew, err;
                two_sum(sacc, sh, tnew, err);
                cacc += ch + err;
                sacc = tnew;
            }
            double v = (double)__shfl_sync(0xffffffffu, sacc, 0) +
                       (double)__shfl_sync(0xffffffffu, cacc, 0);
            if (v > best || (v == best && e < besti)) { best = v; besti = e; }
        }
        if (lane == 0) { bv[wid] = best; bi[wid] = besti; }
        __syncthreads();
        if (threadIdx.x == 0) {
            double m = bv[0]; int am = bi[0];
            for (int w = 1; w < 8; w++)
                if (bv[w] > m || (bv[w] == m && bi[w] < am)) { m = bv[w]; am = bi[w]; }
            g_indices[t] = am;
            out[1 + t] = (float)am;
            float den = 0.0f;
            for (int e = 0; e < EXPERTS; e++) den += __expf(Lsm[e] - mx32);
            out[1 + 2 * T + t] = __expf(Lsm[am] - mx32) / den;
        }
        __syncthreads();
    }
}

// ---------------- pass 4: per-block expert histogram (post-rescue) -----------
__global__ void count_kernel() {
    __shared__ int h[EXPERTS];
    const int t = threadIdx.x;          // 64 threads
    h[t] = 0;
    __syncthreads();
    atomicAdd(&h[g_indices[blockIdx.x * BT + t]], 1);
    __syncthreads();
    g_blockCounts[blockIdx.x * EXPERTS + t] = h[t];
}

// ---------------- pass 5: scan + l_aux ----------------
__global__ void gate_scan(float* __restrict__ out, int T, int nB) {
    __shared__ float red[EXPERTS];
    const int e = threadIdx.x;
    int run = 0;
    for (int b = 0; b < nB; b++) {
        g_blockOffsets[b * EXPERTS + e] = run;
        run += g_blockCounts[b * EXPERTS + e];
    }
    red[e] = g_me[e] * (float)run;
    __syncthreads();
    for (int s = EXPERTS / 2; s > 0; s >>= 1) {
        if (e < s) red[e] += red[e + s];
        __syncthreads();
    }
    if (e == 0)
        out[0] = red[0] * ((float)EXPERTS / ((float)T * (float)T));
}

// ---------------- pass 6: per-token location ----------------
__global__ void gate_loc(float* __restrict__ out, int T) {
    __shared__ int w0cnt[EXPERTS];
    const int b = blockIdx.x;
    const int t = threadIdx.x;
    const int gt = b * BT + t;
    const int e = g_indices[gt];
    const int lane = t & 31;
    const int warp = t >> 5;

    w0cnt[t] = 0;
    __syncthreads();

    unsigned peers = __match_any_sync(0xffffffffu, e);
    int rank = __popc(peers & ((1u << lane) - 1u));
    if (warp == 0 && lane == (__ffs(peers) - 1))
        w0cnt[e] = __popc(peers);
    __syncthreads();

    int loc = g_blockOffsets[b * EXPERTS + e] + rank + (warp ? w0cnt[e] : 0);
    out[1 + T + gt] = (float)loc;
}

// ---------------- launch ----------------
extern "C" void kernel_launch(void* const* d_in, const int* in_sizes, int n_in,
                              void* d_out, int out_size) {
    const float* A = (const float*)d_in[0];
    const float* W = (const float*)d_in[1];
    float* out = (float*)d_out;
    const int T = in_sizes[0] / DIM;        // 8192

    cudaFuncSetAttribute(gemm_kernel, cudaFuncAttributeMaxDynamicSharedMemorySize,
                         SMEM_BYTES);

    init_kernel<<<1, 64>>>();
    gemm_kernel<<<T / MB, GTH, SMEM_BYTES>>>(A, W);
    post_kernel<<<T / BT, 128>>>(out, T);
    rescue_kernel<<<64, 256>>>(A, W, out, T);
    count_kernel<<<T / BT, BT>>>();
    gate_scan<<<1, EXPERTS>>>(out, T, T / BT);
    gate_loc<<<T / BT, BT>>>(out, T);
}

// round 7
// speedup vs baseline: 15.8839x; 1.3841x over previous
#include <cuda_runtime.h>
#include <cstdint>

// ---------------- problem constants ----------------
#define DIM      4096
#define EXPERTS  64
#define T_TOK    8192
#define MB       64                  // tokens per GEMM block
#define BK       64                  // k per stage
#define NSTAGE   (DIM / BK)          // 64
#define GTH      256                 // 8 warps
#define BT       64
#define NB       (T_TOK / BT)        // 128
#define SUSCAP   2048
#define EPS_GAP  5e-4f

// smem layout in uint32 units (bf16x2 packed), USTR=36 -> conflict-free frags
#define USTR     36
#define OFFU_AH  0
#define OFFU_AM  2304                // 64*36
#define OFFU_WH  4608
#define OFFU_WM  6912
#define BUFU     9216
#define SMEM_BYTES (2 * BUFU * 4)    // 73728 B

// ---------------- device scratch ----------------
__device__ float    g_logits[T_TOK * EXPERTS];
__device__ uint32_t g_wh[EXPERTS * (DIM / 2)];   // W hi split, bf16x2
__device__ uint32_t g_wm[EXPERTS * (DIM / 2)];   // W mid split, bf16x2
__device__ float    g_me[EXPERTS];
__device__ int      g_indices[T_TOK];
__device__ int      g_blockCounts[NB * EXPERTS];
__device__ int      g_blockOffsets[NB * EXPERTS];
__device__ int      g_nsus;
__device__ int      g_suspects[SUSCAP];

// ---------------- helpers ----------------
__device__ __forceinline__ uint32_t smem_u32(const void* p) {
    uint32_t a;
    asm("{ .reg .u64 t; cvta.to.shared.u64 t, %1; cvt.u32.u64 %0, t; }" : "=r"(a) : "l"(p));
    return a;
}
// split (x0,x1) fp32 -> hi bf16x2 + mid bf16x2 (residual captured to ~2^-16 rel)
__device__ __forceinline__ void split_bf16x2(float x0, float x1,
                                             uint32_t& h, uint32_t& m) {
    asm("cvt.rn.bf16x2.f32 %0, %1, %2;" : "=r"(h) : "f"(x1), "f"(x0));
    float h0 = __uint_as_float(h << 16);
    float h1 = __uint_as_float(h & 0xFFFF0000u);
    asm("cvt.rn.bf16x2.f32 %0, %1, %2;" : "=r"(m) : "f"(x1 - h1), "f"(x0 - h0));
}
__device__ __forceinline__ void cp16(uint32_t saddr, const void* g) {
    asm volatile("cp.async.cg.shared.global [%0], [%1], 16;" :: "r"(saddr), "l"(g));
}
#define CP_COMMIT() asm volatile("cp.async.commit_group;" ::: "memory")
#define CP_WAIT0()  asm volatile("cp.async.wait_group 0;" ::: "memory")

#define MMA_BF16(d, a, b0, b1)                                               \
    asm volatile(                                                            \
        "mma.sync.aligned.m16n8k16.row.col.f32.bf16.bf16.f32 "               \
        "{%0,%1,%2,%3}, {%4,%5,%6,%7}, {%8,%9}, {%0,%1,%2,%3};"              \
        : "+f"((d)[0]), "+f"((d)[1]), "+f"((d)[2]), "+f"((d)[3])             \
        : "r"((a)[0]), "r"((a)[1]), "r"((a)[2]), "r"((a)[3]),                \
          "r"(b0), "r"(b1))

// ---------------- pass 0: W split precompute + init ----------------
__global__ void wsplit_kernel(const float* __restrict__ W) {
    int i = blockIdx.x * blockDim.x + threadIdx.x;   // pair index
    if (i < EXPERTS * (DIM / 2)) {
        float2 x = reinterpret_cast<const float2*>(W)[i];
        uint32_t h, m;
        split_bf16x2(x.x, x.y, h, m);
        g_wh[i] = h;
        g_wm[i] = m;
    }
    if (i < EXPERTS) g_me[i] = 0.0f;
    if (i == 0) g_nsus = 0;
}

// ---------------- pass 1: 3-product bf16-split mma.sync GEMM ----------------
__global__ __launch_bounds__(GTH, 1) void gemm_kernel(const float* __restrict__ A) {
    extern __shared__ __align__(16) uint32_t smu[];
    const uint32_t sbase = smem_u32(smu);
    const int tid  = threadIdx.x;
    const int lane = tid & 31;
    const int wid  = tid >> 5;       // 8 warps
    const int wm   = wid >> 1;       // 0..3 : 16-token group
    const int wn   = wid & 1;        // 0..1 : 32-expert group
    const int t0   = blockIdx.x * MB;

    float acc[4][4];
#pragma unroll
    for (int ni = 0; ni < 4; ni++)
#pragma unroll
        for (int r = 0; r < 4; r++) acc[ni][r] = 0.0f;

    // prologue: A regs stage 0, W cp.async stage 0
    float4 pA[4];
#pragma unroll
    for (int q = 0; q < 4; q++) {
        int f4 = q * GTH + tid;
        int row = f4 >> 4, c = (f4 & 15) * 4;
        pA[q] = *reinterpret_cast<const float4*>(&A[(size_t)(t0 + row) * DIM + c]);
    }
#pragma unroll
    for (int q = 0; q < 2; q++) {
        int f = q * GTH + tid;               // 0..511
        int row = f >> 3, c = (f & 7) * 4;   // uint32 col
        cp16(sbase + (OFFU_WH + row * USTR + c) * 4, &g_wh[row * (DIM / 2) + c]);
        cp16(sbase + (OFFU_WM + row * USTR + c) * 4, &g_wm[row * (DIM / 2) + c]);
    }
    CP_COMMIT();

    for (int s = 0; s < NSTAGE; s++) {
        uint32_t* buf = smu + (s & 1) * BUFU;
        CP_WAIT0();

        // split-store A tile (bf16 hi/mid)
#pragma unroll
        for (int q = 0; q < 4; q++) {
            int f4 = q * GTH + tid;
            int row = f4 >> 4, c = (f4 & 15) * 4;    // float col
            uint2 h, m;
            split_bf16x2(pA[q].x, pA[q].y, h.x, m.x);
            split_bf16x2(pA[q].z, pA[q].w, h.y, m.y);
            *reinterpret_cast<uint2*>(&buf[OFFU_AH + row * USTR + c / 2]) = h;
            *reinterpret_cast<uint2*>(&buf[OFFU_AM + row * USTR + c / 2]) = m;
        }
        __syncthreads();

        // prefetch stage s+1
        if (s + 1 < NSTAGE) {
            const int k0 = (s + 1) * BK;
#pragma unroll
            for (int q = 0; q < 4; q++) {
                int f4 = q * GTH + tid;
                int row = f4 >> 4, c = (f4 & 15) * 4;
                pA[q] = *reinterpret_cast<const float4*>(&A[(size_t)(t0 + row) * DIM + k0 + c]);
            }
            uint32_t nb = sbase + ((s + 1) & 1) * BUFU * 4;
            const int ku = k0 / 2;
#pragma unroll
            for (int q = 0; q < 2; q++) {
                int f = q * GTH + tid;
                int row = f >> 3, c = (f & 7) * 4;
                cp16(nb + (OFFU_WH + row * USTR + c) * 4, &g_wh[row * (DIM / 2) + ku + c]);
                cp16(nb + (OFFU_WM + row * USTR + c) * 4, &g_wm[row * (DIM / 2) + ku + c]);
            }
            CP_COMMIT();
        }

        // compute: 4 k16 steps
#pragma unroll
        for (int q = 0; q < 4; q++) {
            const int cu = q * 8 + (lane & 3);
            const int r  = wm * 16 + (lane >> 2);
            uint32_t aH[4], aM[4];
            {
                int b0 = OFFU_AH + r * USTR + cu;
                aH[0] = buf[b0];
                aH[1] = buf[b0 + 8 * USTR];
                aH[2] = buf[b0 + 4];
                aH[3] = buf[b0 + 8 * USTR + 4];
                int b1 = OFFU_AM + r * USTR + cu;
                aM[0] = buf[b1];
                aM[1] = buf[b1 + 8 * USTR];
                aM[2] = buf[b1 + 4];
                aM[3] = buf[b1 + 8 * USTR + 4];
            }
#pragma unroll
            for (int ni = 0; ni < 4; ni++) {
                int n = wn * 32 + ni * 8 + (lane >> 2);
                int bb = n * USTR + cu;
                uint32_t bh0 = buf[OFFU_WH + bb], bh1 = buf[OFFU_WH + bb + 4];
                uint32_t bm0 = buf[OFFU_WM + bb], bm1 = buf[OFFU_WM + bb + 4];
                MMA_BF16(acc[ni], aH, bh0, bh1);
                MMA_BF16(acc[ni], aH, bm0, bm1);
                MMA_BF16(acc[ni], aM, bh0, bh1);
            }
        }
    }

    // epilogue: direct store
#pragma unroll
    for (int ni = 0; ni < 4; ni++) {
        int r0 = t0 + wm * 16 + (lane >> 2);
        int c0 = wn * 32 + ni * 8 + (lane & 3) * 2;
        *reinterpret_cast<float2*>(&g_logits[(size_t)r0 * EXPERTS + c0]) =
            make_float2(acc[ni][0], acc[ni][1]);
        *reinterpret_cast<float2*>(&g_logits[(size_t)(r0 + 8) * EXPERTS + c0]) =
            make_float2(acc[ni][2], acc[ni][3]);
    }
}

// ---------------- pass 2: argmax/softmax/me/counts + suspects ----------------
#define LS_STRIDE 68
__global__ void post_kernel(float* __restrict__ out, int T) {
    __shared__ float Ls[BT * LS_STRIDE];
    __shared__ float ms[BT];
    __shared__ float sums[BT];
    __shared__ int   cnt_s[EXPERTS];
    const int tid = threadIdx.x;        // 128 threads
    const int tok0 = blockIdx.x * BT;

#pragma unroll
    for (int q = 0; q < 8; q++) {
        int f4 = q * 128 + tid;
        int row = f4 >> 4, c4 = f4 & 15;
        float4 v = *reinterpret_cast<const float4*>(
            &g_logits[(size_t)(tok0 + row) * EXPERTS + c4 * 4]);
        *reinterpret_cast<float4*>(&Ls[row * LS_STRIDE + c4 * 4]) = v;
    }
    if (tid < EXPERTS) cnt_s[tid] = 0;
    __syncthreads();

    if (tid < BT) {
        const int t = tid;
        float m = Ls[t * LS_STRIDE + 0];
        float m2 = -3.4e38f;
        int am = 0;
#pragma unroll 4
        for (int e = 1; e < EXPERTS; e++) {
            float v = Ls[t * LS_STRIDE + e];
            if (v > m) { m2 = m; m = v; am = e; }
            else if (v > m2) { m2 = v; }
        }
        float s = 0.0f;
#pragma unroll 4
        for (int e = 0; e < EXPERTS; e++)
            s += __expf(Ls[t * LS_STRIDE + e] - m);
        ms[t] = m;
        sums[t] = s;
        int gt = tok0 + t;
        g_indices[gt]       = am;
        out[1 + gt]         = (float)am;
        out[1 + 2 * T + gt] = 1.0f / s;
        atomicAdd(&cnt_s[am], 1);
        if (m - m2 < EPS_GAP) {
            int i = atomicAdd(&g_nsus, 1);
            if (i < SUSCAP) g_suspects[i] = gt;
        }
    }
    __syncthreads();

    if (tid < EXPERTS) {
        const int e = tid;
        float acc = 0.0f;
#pragma unroll 4
        for (int t = 0; t < BT; t++)
            acc += __expf(Ls[t * LS_STRIDE + e] - ms[t]) / sums[t];
        atomicAdd(&g_me[e], acc);
        g_blockCounts[blockIdx.x * EXPERTS + e] = cnt_s[e];
    }
}

// ---------------- pass 3: double-single rescue (adjusts counts) --------------
__device__ __forceinline__ void two_sum(float a, float b, float& s, float& e) {
    s = a + b;
    float bb = s - a;
    e = (a - (s - bb)) + (b - bb);
}

__global__ void rescue_kernel(const float* __restrict__ A,
                              const float* __restrict__ W,
                              float* __restrict__ out, int T) {
    __shared__ float Lsm[EXPERTS];
    __shared__ double bv[8];
    __shared__ int    bi[8];
    const int wid = threadIdx.x >> 5;   // 8 warps
    const int lane = threadIdx.x & 31;
    int n = g_nsus;
    if (n > SUSCAP) n = SUSCAP;

    for (int s = blockIdx.x; s < n; s += gridDim.x) {
        const int t = g_suspects[s];
        const float* ap = A + (size_t)t * DIM;

        if (threadIdx.x < EXPERTS)
            Lsm[threadIdx.x] = g_logits[(size_t)t * EXPERTS + threadIdx.x];
        __syncthreads();
        float mx32 = Lsm[0];
        for (int e = 1; e < EXPERTS; e++) mx32 = fmaxf(mx32, Lsm[e]);
        const float win = mx32 - 2.0f * EPS_GAP;

        double best = -1e300;
        int besti = EXPERTS;
#pragma unroll 1
        for (int sub = 0; sub < 8; sub++) {
            const int e = wid * 8 + sub;
            if (Lsm[e] < win) continue;
            const float* wp = W + (size_t)e * DIM;
            float sacc = 0.0f, cacc = 0.0f;
#pragma unroll 4
            for (int i = 0; i < DIM / 128; i++) {
                int k = (i * 32 + lane) * 4;
                float4 av = *reinterpret_cast<const float4*>(ap + k);
                float4 wv = *reinterpret_cast<const float4*>(wp + k);
#pragma unroll
                for (int j = 0; j < 4; j++) {
                    float a = (&av.x)[j], b = (&wv.x)[j];
                    float p = a * b;
                    float pe = fmaf(a, b, -p);
                    float tnew, err;
                    two_sum(sacc, p, tnew, err);
                    cacc += err + pe;
                    sacc = tnew;
                }
            }
#pragma unroll
            for (int o = 16; o; o >>= 1) {
                float sh = __shfl_down_sync(0xffffffffu, sacc, o);
                float ch = __shfl_down_sync(0xffffffffu, cacc, o);
                float tnew, err;
                two_sum(sacc, sh, tnew, err);
                cacc += ch + err;
                sacc = tnew;
            }
            double v = (double)__shfl_sync(0xffffffffu, sacc, 0) +
                       (double)__shfl_sync(0xffffffffu, cacc, 0);
            if (v > best || (v == best && e < besti)) { best = v; besti = e; }
        }
        if (lane == 0) { bv[wid] = best; bi[wid] = besti; }
        __syncthreads();
        if (threadIdx.x == 0) {
            double m = bv[0]; int am = bi[0];
            for (int w = 1; w < 8; w++)
                if (bv[w] > m || (bv[w] == m && bi[w] < am)) { m = bv[w]; am = bi[w]; }
            int old = g_indices[t];
            if (am != old) {
                int blk = t / BT;
                atomicSub(&g_blockCounts[blk * EXPERTS + old], 1);
                atomicAdd(&g_blockCounts[blk * EXPERTS + am], 1);
                g_indices[t] = am;
                out[1 + t] = (float)am;
            }
            float den = 0.0f;
            for (int e = 0; e < EXPERTS; e++) den += __expf(Lsm[e] - mx32);
            out[1 + 2 * T + t] = __expf(Lsm[am] - mx32) / den;
        }
        __syncthreads();
    }
}

// ---------------- pass 4: scan + l_aux ----------------
__global__ void gate_scan(float* __restrict__ out, int T, int nB) {
    __shared__ float red[EXPERTS];
    const int e = threadIdx.x;
    int run = 0;
    for (int b = 0; b < nB; b++) {
        g_blockOffsets[b * EXPERTS + e] = run;
        run += g_blockCounts[b * EXPERTS + e];
    }
    red[e] = g_me[e] * (float)run;
    __syncthreads();
    for (int s = EXPERTS / 2; s > 0; s >>= 1) {
        if (e < s) red[e] += red[e + s];
        __syncthreads();
    }
    if (e == 0)
        out[0] = red[0] * ((float)EXPERTS / ((float)T * (float)T));
}

// ---------------- pass 5: per-token location ----------------
__global__ void gate_loc(float* __restrict__ out, int T) {
    __shared__ int w0cnt[EXPERTS];
    const int b = blockIdx.x;
    const int t = threadIdx.x;
    const int gt = b * BT + t;
    const int e = g_indices[gt];
    const int lane = t & 31;
    const int warp = t >> 5;

    w0cnt[t] = 0;
    __syncthreads();

    unsigned peers = __match_any_sync(0xffffffffu, e);
    int rank = __popc(peers & ((1u << lane) - 1u));
    if (warp == 0 && lane == (__ffs(peers) - 1))
        w0cnt[e] = __popc(peers);
    __syncthreads();

    int loc = g_blockOffsets[b * EXPERTS + e] + rank + (warp ? w0cnt[e] : 0);
    out[1 + T + gt] = (float)loc;
}

// ---------------- launch ----------------
extern "C" void kernel_launch(void* const* d_in, const int* in_sizes, int n_in,
                              void* d_out, int out_size) {
    const float* A = (const float*)d_in[0];
    const float* W = (const float*)d_in[1];
    float* out = (float*)d_out;
    const int T = in_sizes[0] / DIM;        // 8192

    cudaFuncSetAttribute(gemm_kernel, cudaFuncAttributeMaxDynamicSharedMemorySize,
                         SMEM_BYTES);

    wsplit_kernel<<<(EXPERTS * (DIM / 2) + 255) / 256, 256>>>(W);
    gemm_kernel<<<T / MB, GTH, SMEM_BYTES>>>(A);
    post_kernel<<<T / BT, 128>>>(out, T);
    rescue_kernel<<<32, 256>>>(A, W, out, T);
    gate_scan<<<1, EXPERTS>>>(out, T, T / BT);
    gate_loc<<<T / BT, BT>>>(out, T);
}

// round 8
// speedup vs baseline: 20.9548x; 1.3192x over previous
#include <cuda_runtime.h>
#include <cuda_fp16.h>
#include <cstdint>

// ---------------- problem constants ----------------
#define DIM      4096
#define EXPERTS  64
#define T_TOK    8192
#define MB       64                  // tokens per GEMM block
#define BK       64                  // k per stage
#define NSTAGE   (DIM / BK)          // 64
#define GTH      256                 // 8 warps
#define BT       64
#define NB       (T_TOK / BT)        // 128
#define SUSCAP   2048
#define EPS_GAP  1e-5f

// smem layout in uint32 units (fp16x2 packed), USTR=36 -> conflict-free frags
#define USTR     36
#define OFFU_AH  0
#define OFFU_AM  2304                // 64*36
#define OFFU_WH  4608
#define OFFU_WM  6912
#define BUFU     9216
#define SMEM_BYTES (2 * BUFU * 4)    // 73728 B (also covers 64x65 epi floats)

// ---------------- device scratch ----------------
__device__ float    g_logits[T_TOK * EXPERTS];
__device__ uint32_t g_wh[EXPERTS * (DIM / 2)];   // W hi split, fp16x2
__device__ uint32_t g_wm[EXPERTS * (DIM / 2)];   // W mid split, fp16x2
__device__ float    g_me[EXPERTS];
__device__ int      g_indices[T_TOK];
__device__ int      g_blockCounts[NB * EXPERTS];
__device__ int      g_blockOffsets[NB * EXPERTS];
__device__ int      g_nsus;
__device__ int      g_suspects[SUSCAP];

// ---------------- helpers ----------------
__device__ __forceinline__ uint32_t smem_u32(const void* p) {
    uint32_t a;
    asm("{ .reg .u64 t; cvta.to.shared.u64 t, %1; cvt.u32.u64 %0, t; }" : "=r"(a) : "l"(p));
    return a;
}
// split (x0,x1) fp32 -> hi fp16x2 + mid fp16x2 (captures ~22 mantissa bits)
__device__ __forceinline__ void split_f16x2(float x0, float x1,
                                            uint32_t& h, uint32_t& m) {
    __half2 h2 = __floats2half2_rn(x0, x1);
    h = *reinterpret_cast<uint32_t*>(&h2);
    float r0 = x0 - __low2float(h2);
    float r1 = x1 - __high2float(h2);
    __half2 m2 = __floats2half2_rn(r0, r1);
    m = *reinterpret_cast<uint32_t*>(&m2);
}
__device__ __forceinline__ void cp16(uint32_t saddr, const void* g) {
    asm volatile("cp.async.cg.shared.global [%0], [%1], 16;" :: "r"(saddr), "l"(g));
}
#define CP_COMMIT() asm volatile("cp.async.commit_group;" ::: "memory")
#define CP_WAIT0()  asm volatile("cp.async.wait_group 0;" ::: "memory")

#define MMA_FP16(d, a, b0, b1)                                               \
    asm volatile(                                                            \
        "mma.sync.aligned.m16n8k16.row.col.f32.f16.f16.f32 "                 \
        "{%0,%1,%2,%3}, {%4,%5,%6,%7}, {%8,%9}, {%0,%1,%2,%3};"              \
        : "+f"((d)[0]), "+f"((d)[1]), "+f"((d)[2]), "+f"((d)[3])             \
        : "r"((a)[0]), "r"((a)[1]), "r"((a)[2]), "r"((a)[3]),                \
          "r"(b0), "r"(b1))

// ---------------- pass 0: W split precompute + init ----------------
__global__ void wsplit_kernel(const float* __restrict__ W) {
    int i = blockIdx.x * blockDim.x + threadIdx.x;   // pair index
    if (i < EXPERTS * (DIM / 2)) {
        float2 x = reinterpret_cast<const float2*>(W)[i];
        uint32_t h, m;
        split_f16x2(x.x, x.y, h, m);
        g_wh[i] = h;
        g_wm[i] = m;
    }
    if (i < EXPERTS) g_me[i] = 0.0f;
    if (i == 0) g_nsus = 0;
}

// ---------------- pass 1: fp16-split GEMM + fused gate epilogue -------------
#define ESTR 65
__global__ __launch_bounds__(GTH, 1) void gemm_kernel(
    const float* __restrict__ A, float* __restrict__ out, int T)
{
    extern __shared__ __align__(16) uint32_t smu[];
    const uint32_t sbase = smem_u32(smu);
    const int tid  = threadIdx.x;
    const int lane = tid & 31;
    const int wid  = tid >> 5;       // 8 warps
    const int wm   = wid >> 1;       // 0..3 : 16-token group
    const int wn   = wid & 1;        // 0..1 : 32-expert group
    const int t0   = blockIdx.x * MB;

    float acc[4][4];
#pragma unroll
    for (int ni = 0; ni < 4; ni++)
#pragma unroll
        for (int r = 0; r < 4; r++) acc[ni][r] = 0.0f;

    // prologue: A regs stage 0, W cp.async stage 0
    float4 pA[4];
#pragma unroll
    for (int q = 0; q < 4; q++) {
        int f4 = q * GTH + tid;
        int row = f4 >> 4, c = (f4 & 15) * 4;
        pA[q] = *reinterpret_cast<const float4*>(&A[(size_t)(t0 + row) * DIM + c]);
    }
#pragma unroll
    for (int q = 0; q < 2; q++) {
        int f = q * GTH + tid;               // 0..511
        int row = f >> 3, c = (f & 7) * 4;   // uint32 col
        cp16(sbase + (OFFU_WH + row * USTR + c) * 4, &g_wh[row * (DIM / 2) + c]);
        cp16(sbase + (OFFU_WM + row * USTR + c) * 4, &g_wm[row * (DIM / 2) + c]);
    }
    CP_COMMIT();

    for (int s = 0; s < NSTAGE; s++) {
        uint32_t* buf = smu + (s & 1) * BUFU;
        CP_WAIT0();

        // split-store A tile (fp16 hi/mid)
#pragma unroll
        for (int q = 0; q < 4; q++) {
            int f4 = q * GTH + tid;
            int row = f4 >> 4, c = (f4 & 15) * 4;    // float col
            uint2 h, m;
            split_f16x2(pA[q].x, pA[q].y, h.x, m.x);
            split_f16x2(pA[q].z, pA[q].w, h.y, m.y);
            *reinterpret_cast<uint2*>(&buf[OFFU_AH + row * USTR + c / 2]) = h;
            *reinterpret_cast<uint2*>(&buf[OFFU_AM + row * USTR + c / 2]) = m;
        }
        __syncthreads();

        // prefetch stage s+1
        if (s + 1 < NSTAGE) {
            const int k0 = (s + 1) * BK;
#pragma unroll
            for (int q = 0; q < 4; q++) {
                int f4 = q * GTH + tid;
                int row = f4 >> 4, c = (f4 & 15) * 4;
                pA[q] = *reinterpret_cast<const float4*>(&A[(size_t)(t0 + row) * DIM + k0 + c]);
            }
            uint32_t nb = sbase + ((s + 1) & 1) * BUFU * 4;
            const int ku = k0 / 2;
#pragma unroll
            for (int q = 0; q < 2; q++) {
                int f = q * GTH + tid;
                int row = f >> 3, c = (f & 7) * 4;
                cp16(nb + (OFFU_WH + row * USTR + c) * 4, &g_wh[row * (DIM / 2) + ku + c]);
                cp16(nb + (OFFU_WM + row * USTR + c) * 4, &g_wm[row * (DIM / 2) + ku + c]);
            }
            CP_COMMIT();
        }

        // compute: 4 k16 steps
#pragma unroll
        for (int q = 0; q < 4; q++) {
            const int cu = q * 8 + (lane & 3);
            const int r  = wm * 16 + (lane >> 2);
            uint32_t aH[4], aM[4];
            {
                int b0 = OFFU_AH + r * USTR + cu;
                aH[0] = buf[b0];
                aH[1] = buf[b0 + 8 * USTR];
                aH[2] = buf[b0 + 4];
                aH[3] = buf[b0 + 8 * USTR + 4];
                int b1 = OFFU_AM + r * USTR + cu;
                aM[0] = buf[b1];
                aM[1] = buf[b1 + 8 * USTR];
                aM[2] = buf[b1 + 4];
                aM[3] = buf[b1 + 8 * USTR + 4];
            }
#pragma unroll
            for (int ni = 0; ni < 4; ni++) {
                int n = wn * 32 + ni * 8 + (lane >> 2);
                int bb = n * USTR + cu;
                uint32_t bh0 = buf[OFFU_WH + bb], bh1 = buf[OFFU_WH + bb + 4];
                uint32_t bm0 = buf[OFFU_WM + bb], bm1 = buf[OFFU_WM + bb + 4];
                MMA_FP16(acc[ni], aH, bh0, bh1);
                MMA_FP16(acc[ni], aH, bm0, bm1);
                MMA_FP16(acc[ni], aM, bh0, bh1);
            }
        }
    }

    // ---- fused epilogue ----
    __syncthreads();                       // everyone done reading buffers
    float* epi = reinterpret_cast<float*>(smu);      // [64][65]
#pragma unroll
    for (int ni = 0; ni < 4; ni++) {
        int r0 = wm * 16 + (lane >> 2);
        int c0 = wn * 32 + ni * 8 + (lane & 3) * 2;
        epi[r0 * ESTR + c0]           = acc[ni][0];
        epi[r0 * ESTR + c0 + 1]       = acc[ni][1];
        epi[(r0 + 8) * ESTR + c0]     = acc[ni][2];
        epi[(r0 + 8) * ESTR + c0 + 1] = acc[ni][3];
        // gmem logits (write-only; rescue reads them)
        *reinterpret_cast<float2*>(&g_logits[(size_t)(t0 + r0) * EXPERTS + c0]) =
            make_float2(acc[ni][0], acc[ni][1]);
        *reinterpret_cast<float2*>(&g_logits[(size_t)(t0 + r0 + 8) * EXPERTS + c0]) =
            make_float2(acc[ni][2], acc[ni][3]);
    }
    __shared__ float ms[MB];
    __shared__ float sums[MB];
    __shared__ int   cnt_s[EXPERTS];
    if (tid < EXPERTS) cnt_s[tid] = 0;
    __syncthreads();

    if (tid < MB) {
        const int t = tid;
        float m = epi[t * ESTR + 0];
        float m2 = -3.4e38f;
        int am = 0;
#pragma unroll 4
        for (int e = 1; e < EXPERTS; e++) {
            float v = epi[t * ESTR + e];
            if (v > m) { m2 = m; m = v; am = e; }
            else if (v > m2) { m2 = v; }
        }
        float ssum = 0.0f;
#pragma unroll 4
        for (int e = 0; e < EXPERTS; e++)
            ssum += __expf(epi[t * ESTR + e] - m);
        ms[t] = m;
        sums[t] = ssum;
        int gt = t0 + t;
        g_indices[gt]       = am;
        out[1 + gt]         = (float)am;
        out[1 + 2 * T + gt] = 1.0f / ssum;
        atomicAdd(&cnt_s[am], 1);
        if (m - m2 < EPS_GAP) {
            int i = atomicAdd(&g_nsus, 1);
            if (i < SUSCAP) g_suspects[i] = gt;
        }
    }
    __syncthreads();

    if (tid < EXPERTS) {
        const int e = tid;
        float accm = 0.0f;
#pragma unroll 4
        for (int t = 0; t < MB; t++)
            accm += __expf(epi[t * ESTR + e] - ms[t]) / sums[t];
        atomicAdd(&g_me[e], accm);
        g_blockCounts[blockIdx.x * EXPERTS + e] = cnt_s[e];
    }
}

// ---------------- pass 2: double-single rescue (adjusts counts) --------------
__device__ __forceinline__ void two_sum(float a, float b, float& s, float& e) {
    s = a + b;
    float bb = s - a;
    e = (a - (s - bb)) + (b - bb);
}

__global__ void rescue_kernel(const float* __restrict__ A,
                              const float* __restrict__ W,
                              float* __restrict__ out, int T) {
    __shared__ float Lsm[EXPERTS];
    __shared__ double bv[8];
    __shared__ int    bi[8];
    const int wid = threadIdx.x >> 5;   // 8 warps
    const int lane = threadIdx.x & 31;
    int n = g_nsus;
    if (n > SUSCAP) n = SUSCAP;

    for (int s = blockIdx.x; s < n; s += gridDim.x) {
        const int t = g_suspects[s];
        const float* ap = A + (size_t)t * DIM;

        if (threadIdx.x < EXPERTS)
            Lsm[threadIdx.x] = g_logits[(size_t)t * EXPERTS + threadIdx.x];
        __syncthreads();
        float mx32 = Lsm[0];
        for (int e = 1; e < EXPERTS; e++) mx32 = fmaxf(mx32, Lsm[e]);
        const float win = mx32 - 2.0f * EPS_GAP;

        double best = -1e300;
        int besti = EXPERTS;
#pragma unroll 1
        for (int sub = 0; sub < 8; sub++) {
            const int e = wid * 8 + sub;
            if (Lsm[e] < win) continue;
            const float* wp = W + (size_t)e * DIM;
            float sacc = 0.0f, cacc = 0.0f;
#pragma unroll 4
            for (int i = 0; i < DIM / 128; i++) {
                int k = (i * 32 + lane) * 4;
                float4 av = *reinterpret_cast<const float4*>(ap + k);
                float4 wv = *reinterpret_cast<const float4*>(wp + k);
#pragma unroll
                for (int j = 0; j < 4; j++) {
                    float a = (&av.x)[j], b = (&wv.x)[j];
                    float p = a * b;
                    float pe = fmaf(a, b, -p);
                    float tnew, err;
                    two_sum(sacc, p, tnew, err);
                    cacc += err + pe;
                    sacc = tnew;
                }
            }
#pragma unroll
            for (int o = 16; o; o >>= 1) {
                float sh = __shfl_down_sync(0xffffffffu, sacc, o);
                float ch = __shfl_down_sync(0xffffffffu, cacc, o);
                float tnew, err;
                two_sum(sacc, sh, tnew, err);
                cacc += ch + err;
                sacc = tnew;
            }
            double v = (double)__shfl_sync(0xffffffffu, sacc, 0) +
                       (double)__shfl_sync(0xffffffffu, cacc, 0);
            if (v > best || (v == best && e < besti)) { best = v; besti = e; }
        }
        if (lane == 0) { bv[wid] = best; bi[wid] = besti; }
        __syncthreads();
        if (threadIdx.x == 0) {
            double m = bv[0]; int am = bi[0];
            for (int w = 1; w < 8; w++)
                if (bv[w] > m || (bv[w] == m && bi[w] < am)) { m = bv[w]; am = bi[w]; }
            int old = g_indices[t];
            if (am != old) {
                int blk = t / BT;
                atomicSub(&g_blockCounts[blk * EXPERTS + old], 1);
                atomicAdd(&g_blockCounts[blk * EXPERTS + am], 1);
                g_indices[t] = am;
                out[1 + t] = (float)am;
            }
            float den = 0.0f;
            for (int e = 0; e < EXPERTS; e++) den += __expf(Lsm[e] - mx32);
            out[1 + 2 * T + t] = __expf(Lsm[am] - mx32) / den;
        }
        __syncthreads();
    }
}

// ---------------- pass 3: scan + l_aux ----------------
__global__ void gate_scan(float* __restrict__ out, int T, int nB) {
    __shared__ float red[EXPERTS];
    const int e = threadIdx.x;
    int run = 0;
    for (int b = 0; b < nB; b++) {
        g_blockOffsets[b * EXPERTS + e] = run;
        run += g_blockCounts[b * EXPERTS + e];
    }
    red[e] = g_me[e] * (float)run;
    __syncthreads();
    for (int s = EXPERTS / 2; s > 0; s >>= 1) {
        if (e < s) red[e] += red[e + s];
        __syncthreads();
    }
    if (e == 0)
        out[0] = red[0] * ((float)EXPERTS / ((float)T * (float)T));
}

// ---------------- pass 4: per-token location ----------------
__global__ void gate_loc(float* __restrict__ out, int T) {
    __shared__ int w0cnt[EXPERTS];
    const int b = blockIdx.x;
    const int t = threadIdx.x;
    const int gt = b * BT + t;
    const int e = g_indices[gt];
    const int lane = t & 31;
    const int warp = t >> 5;

    w0cnt[t] = 0;
    __syncthreads();

    unsigned peers = __match_any_sync(0xffffffffu, e);
    int rank = __popc(peers & ((1u << lane) - 1u));
    if (warp == 0 && lane == (__ffs(peers) - 1))
        w0cnt[e] = __popc(peers);
    __syncthreads();

    int loc = g_blockOffsets[b * EXPERTS + e] + rank + (warp ? w0cnt[e] : 0);
    out[1 + T + gt] = (float)loc;
}

// ---------------- launch ----------------
extern "C" void kernel_launch(void* const* d_in, const int* in_sizes, int n_in,
                              void* d_out, int out_size) {
    const float* A = (const float*)d_in[0];
    const float* W = (const float*)d_in[1];
    float* out = (float*)d_out;
    const int T = in_sizes[0] / DIM;        // 8192

    cudaFuncSetAttribute(gemm_kernel, cudaFuncAttributeMaxDynamicSharedMemorySize,
                         SMEM_BYTES);

    wsplit_kernel<<<(EXPERTS * (DIM / 2) + 255) / 256, 256>>>(W);
    gemm_kernel<<<T / MB, GTH, SMEM_BYTES>>>(A, out, T);
    rescue_kernel<<<128, 256>>>(A, W, out, T);
    gate_scan<<<1, EXPERTS>>>(out, T, T / BT);
    gate_loc<<<T / BT, BT>>>(out, T);
}